// round 3
// baseline (speedup 1.0000x reference)
#include <cuda_runtime.h>
#include <float.h>
#include <stdint.h>

// Fixed problem shape
#define KC   512            // codebook size
#define DC   64             // code dim
#define HWC  4096           // H*W
#define NC   131072         // B*H*W
#define TPB  256
#define GRID (NC / TPB)     // 512 blocks
#define ETS  520            // padded row stride for transposed codebook (floats)

// smem floats: ET[64][520] + enorm[512] + red[256]
#define ET_FLOATS   (DC * ETS)
#define SMEM_FLOATS (ET_FLOATS + KC + TPB)
#define SMEM_BYTES  (SMEM_FLOATS * 4)

__device__ float    g_part[GRID];
__device__ unsigned g_cnt;          // zero-initialized; self-resets each launch

typedef unsigned long long u64;

__device__ __forceinline__ u64 pack2(float x, float y) {
    u64 r;
    asm("mov.b64 %0, {%1, %2};" : "=l"(r) : "f"(x), "f"(y));
    return r;
}
__device__ __forceinline__ void unpack2(u64 v, float& x, float& y) {
    asm("mov.b64 {%0, %1}, %2;" : "=f"(x), "=f"(y) : "l"(v));
}
__device__ __forceinline__ u64 ffma2(u64 a, u64 b, u64 c) {
    u64 d;
    asm("fma.rn.f32x2 %0, %1, %2, %3;" : "=l"(d) : "l"(a), "l"(b), "l"(c));
    return d;
}

__global__ __launch_bounds__(TPB)
void vq_kernel(const float* __restrict__ latents,
               const float* __restrict__ embedding,
               float* __restrict__ out,
               float* __restrict__ loss_out) {
    extern __shared__ float smem[];
    float* ET    = smem;                 // [64][520], ET[d*ETS + k]
    float* eNorm = smem + ET_FLOATS;     // [512]
    float* red   = eNorm + KC;           // [256]

    const int tid = threadIdx.x;

    // ---- stage transposed codebook (coalesced gmem read, scattered STS) ----
    {
        const float4* src = reinterpret_cast<const float4*>(embedding);
        #pragma unroll
        for (int i4 = tid; i4 < (KC * DC) / 4; i4 += TPB) {
            float4 v = src[i4];
            int i = i4 * 4;
            int k = i >> 6;        // i / 64
            int d = i & 63;        // i % 64
            ET[(d + 0) * ETS + k] = v.x;
            ET[(d + 1) * ETS + k] = v.y;
            ET[(d + 2) * ETS + k] = v.z;
            ET[(d + 3) * ETS + k] = v.w;
        }
    }
    __syncthreads();

    // ---- enorm_k: sequential d, separate mul/add rounding (XLA reduce emulation) ----
    #pragma unroll
    for (int k = tid; k < KC; k += TPB) {
        float s = 0.0f;
        #pragma unroll
        for (int d = 0; d < DC; ++d) {
            float e = ET[d * ETS + k];
            s = __fadd_rn(s, __fmul_rn(e, e));
        }
        eNorm[k] = s;
    }
    __syncthreads();

    // ---- this thread's pixel ----
    const int p  = blockIdx.x * TPB + tid;
    const int b  = p >> 12;
    const int hw = p & (HWC - 1);
    const float* lat = latents + (size_t)b * DC * HWC + hw;

    float f[DC];
    #pragma unroll
    for (int d = 0; d < DC; ++d) f[d] = lat[d * HWC];

    // fnorm: sequential d, separate mul/add
    float fnorm = 0.0f;
    #pragma unroll
    for (int d = 0; d < DC; ++d) fnorm = __fadd_rn(fnorm, __fmul_rn(f[d], f[d]));

    // ---- argmin: dist_k = fl( fl(fnorm+enorm_k) - fl(2*dot_k) ) ----
    // dot_k = sequential fp32 FMA chain over d (Eigen GEMM emulation); one chain
    // per f32x2 lane, 16 codes (8 lanes-pairs) per block.
    float best  = FLT_MAX;
    int   bestk = 0;

    #pragma unroll 1
    for (int k0 = 0; k0 < KC; k0 += 16) {
        u64 a0 = 0, a1 = 0, a2 = 0, a3 = 0, a4 = 0, a5 = 0, a6 = 0, a7 = 0;
        // 0ull == {+0.f, +0.f}

        #pragma unroll 8
        for (int d = 0; d < DC; ++d) {
            const u64 f2 = pack2(f[d], f[d]);
            const float4* row4 = reinterpret_cast<const float4*>(ET + d * ETS + k0);
            float4 e0 = row4[0];
            float4 e1 = row4[1];
            float4 e2 = row4[2];
            float4 e3 = row4[3];
            a0 = ffma2(f2, pack2(e0.x, e0.y), a0);
            a1 = ffma2(f2, pack2(e0.z, e0.w), a1);
            a2 = ffma2(f2, pack2(e1.x, e1.y), a2);
            a3 = ffma2(f2, pack2(e1.z, e1.w), a3);
            a4 = ffma2(f2, pack2(e2.x, e2.y), a4);
            a5 = ffma2(f2, pack2(e2.z, e2.w), a5);
            a6 = ffma2(f2, pack2(e3.x, e3.y), a6);
            a7 = ffma2(f2, pack2(e3.z, e3.w), a7);
        }

        float dots[16];
        unpack2(a0, dots[0],  dots[1]);
        unpack2(a1, dots[2],  dots[3]);
        unpack2(a2, dots[4],  dots[5]);
        unpack2(a3, dots[6],  dots[7]);
        unpack2(a4, dots[8],  dots[9]);
        unpack2(a5, dots[10], dots[11]);
        unpack2(a6, dots[12], dots[13]);
        unpack2(a7, dots[14], dots[15]);

        #pragma unroll
        for (int j = 0; j < 16; ++j) {
            int k = k0 + j;
            float t = __fadd_rn(fnorm, eNorm[k]);     // fl(fnorm + enorm)
            float u = __fmul_rn(2.0f, dots[j]);       // fl(2*dot)
            float s = __fsub_rn(t, u);                // fl(dist)
            bestk = (s < best) ? k : bestk;           // strict < => first-min
            best  = fminf(s, best);
        }
    }

    // ---- epilogue: gather code, STE output, per-pixel loss partial ----
    float* outp = out + (size_t)b * DC * HWC + hw;
    float ldist = 0.0f;
    #pragma unroll
    for (int d = 0; d < DC; ++d) {
        float q  = ET[d * ETS + bestk];
        float fd = f[d];
        float dq = __fsub_rn(q, fd);                  // fl(q - lat)
        ldist = __fadd_rn(ldist, __fmul_rn(dq, dq));
        outp[d * HWC] = __fadd_rn(fd, dq);            // fl(lat + (q - lat))  (STE)
    }

    // ---- block reduce loss (deterministic tree) ----
    red[tid] = ldist;
    __syncthreads();
    #pragma unroll
    for (int s = TPB / 2; s > 0; s >>= 1) {
        if (tid < s) red[tid] += red[tid + s];
        __syncthreads();
    }
    if (tid == 0) g_part[blockIdx.x] = red[0];

    // ---- last block finalizes (single-kernel grid reduction) ----
    __shared__ unsigned s_last;
    __threadfence();
    if (tid == 0) s_last = (atomicAdd(&g_cnt, 1u) == GRID - 1u);
    __syncthreads();

    if (s_last) {
        // deterministic tree over the 512 partials
        red[tid] = g_part[tid] + g_part[tid + TPB];
        __syncthreads();
        #pragma unroll
        for (int s = TPB / 2; s > 0; s >>= 1) {
            if (tid < s) red[tid] += red[tid + s];
            __syncthreads();
        }
        if (tid == 0) {
            float m = red[0] / 8388608.0f;                   // mean, exact /2^23
            *loss_out = __fadd_rn(__fmul_rn(m, 0.25f), m);   // fl(0.25m) + m
            g_cnt = 0;                                       // reset for next replay
        }
    }
}

extern "C" void kernel_launch(void* const* d_in, const int* in_sizes, int n_in,
                              void* d_out, int out_size) {
    const float* latents   = (const float*)d_in[0];   // [32, 64, 64, 64] fp32
    const float* embedding = (const float*)d_in[1];   // [512, 64] fp32
    float* out  = (float*)d_out;                      // tensor, then loss scalar
    float* loss = out + (out_size - 1);

    cudaFuncSetAttribute(vq_kernel, cudaFuncAttributeMaxDynamicSharedMemorySize, SMEM_BYTES);
    vq_kernel<<<GRID, TPB, SMEM_BYTES>>>(latents, embedding, out, loss);
}

// round 4
// speedup vs baseline: 1.2341x; 1.2341x over previous
#include <cuda_runtime.h>
#include <float.h>
#include <stdint.h>

// Fixed problem shape
#define KC     512          // codebook size
#define DC     64           // code dim
#define HWC    4096         // H*W
#define NC     131072       // B*H*W
#define TPB    256
#define NTILES (NC / TPB)   // 512 tiles of 256 pixels
#define GRIDP  152          // persistent CTAs (GB300: 152 SMs)
#define ETS    520          // padded row stride (floats); 520*4=2080B, 16B-aligned rows

// smem floats: ET[64][520] + enorm[512] + red[256]
#define ET_FLOATS   (DC * ETS)
#define SMEM_FLOATS (ET_FLOATS + KC + TPB)
#define SMEM_BYTES  (SMEM_FLOATS * 4)

__device__ float    g_part[NTILES];
__device__ unsigned g_done;         // zero-init; finalizer resets each launch

typedef unsigned long long u64;

__device__ __forceinline__ u64 pack2(float x, float y) {
    u64 r;
    asm("mov.b64 %0, {%1, %2};" : "=l"(r) : "f"(x), "f"(y));
    return r;
}
__device__ __forceinline__ void unpack2(u64 v, float& x, float& y) {
    asm("mov.b64 {%0, %1}, %2;" : "=f"(x), "=f"(y) : "l"(v));
}
__device__ __forceinline__ u64 ffma2(u64 a, u64 b, u64 c) {
    u64 d;
    asm("fma.rn.f32x2 %0, %1, %2, %3;" : "=l"(d) : "l"(a), "l"(b), "l"(c));
    return d;
}

__global__ __launch_bounds__(TPB)
void vq_kernel(const float* __restrict__ latents,
               const float* __restrict__ embedding,
               float* __restrict__ out,
               float* __restrict__ loss_out) {
    extern __shared__ float smem[];
    float* ET    = smem;                 // [64][520], ET[d*ETS + k]
    float* eNorm = smem + ET_FLOATS;     // [512]
    float* red   = eNorm + KC;           // [256]

    const int tid = threadIdx.x;

    // ---- stage transposed codebook once per CTA ----
    {
        const float4* src = reinterpret_cast<const float4*>(embedding);
        #pragma unroll
        for (int i4 = tid; i4 < (KC * DC) / 4; i4 += TPB) {
            float4 v = src[i4];
            int i = i4 * 4;
            int k = i >> 6;
            int d = i & 63;
            ET[(d + 0) * ETS + k] = v.x;
            ET[(d + 1) * ETS + k] = v.y;
            ET[(d + 2) * ETS + k] = v.z;
            ET[(d + 3) * ETS + k] = v.w;
        }
    }
    __syncthreads();

    // ---- enorm_k: sequential d, separate mul/add (XLA reduce emulation) ----
    #pragma unroll
    for (int k = tid; k < KC; k += TPB) {
        float s = 0.0f;
        #pragma unroll
        for (int d = 0; d < DC; ++d) {
            float e = ET[d * ETS + k];
            s = __fadd_rn(s, __fmul_rn(e, e));
        }
        eNorm[k] = s;
    }
    __syncthreads();

    // ---- persistent tile loop ----
    for (int tile = blockIdx.x; tile < NTILES; tile += GRIDP) {
        const int p  = tile * TPB + tid;
        const int b  = p >> 12;
        const int hw = p & (HWC - 1);
        const float* lat = latents + (size_t)b * DC * HWC + hw;

        // load latent, pre-pack {f,f} pairs, fnorm (sequential mul/add)
        u64   f2[DC];
        float fnorm = 0.0f;
        #pragma unroll
        for (int d = 0; d < DC; ++d) {
            float fd = lat[d * HWC];
            f2[d] = pack2(fd, fd);
            fnorm = __fadd_rn(fnorm, __fmul_rn(fd, fd));
        }

        // ---- argmin: dist_k = fl( fl(fnorm+enorm_k) - fl(2*dot_k) ) ----
        // dot_k: sequential fp32 FMA chain over d, one chain per f32x2 lane.
        float best  = FLT_MAX;
        int   bestk = 0;

        #pragma unroll 1
        for (int k0 = 0; k0 < KC; k0 += 16) {
            u64 a0 = 0, a1 = 0, a2 = 0, a3 = 0, a4 = 0, a5 = 0, a6 = 0, a7 = 0;

            #pragma unroll
            for (int d = 0; d < DC; ++d) {
                // 16 codes for this d: 64B = 4x LDS.128, operands pre-paired
                const ulonglong2* row =
                    reinterpret_cast<const ulonglong2*>(ET + d * ETS + k0);
                ulonglong2 e01 = row[0];
                ulonglong2 e23 = row[1];
                ulonglong2 e45 = row[2];
                ulonglong2 e67 = row[3];
                const u64 m = f2[d];
                a0 = ffma2(m, e01.x, a0);
                a1 = ffma2(m, e01.y, a1);
                a2 = ffma2(m, e23.x, a2);
                a3 = ffma2(m, e23.y, a3);
                a4 = ffma2(m, e45.x, a4);
                a5 = ffma2(m, e45.y, a5);
                a6 = ffma2(m, e67.x, a6);
                a7 = ffma2(m, e67.y, a7);
            }

            float dots[16];
            unpack2(a0, dots[0],  dots[1]);
            unpack2(a1, dots[2],  dots[3]);
            unpack2(a2, dots[4],  dots[5]);
            unpack2(a3, dots[6],  dots[7]);
            unpack2(a4, dots[8],  dots[9]);
            unpack2(a5, dots[10], dots[11]);
            unpack2(a6, dots[12], dots[13]);
            unpack2(a7, dots[14], dots[15]);

            #pragma unroll
            for (int j = 0; j < 16; ++j) {
                int k = k0 + j;
                float t = __fadd_rn(fnorm, eNorm[k]);   // fl(fnorm + enorm)
                float u = __fmul_rn(2.0f, dots[j]);     // fl(2*dot)
                float s = __fsub_rn(t, u);              // fl(dist)
                bestk = (s < best) ? k : bestk;         // strict < => first-min
                best  = fminf(s, best);
            }
        }

        // ---- epilogue: gather code, STE output, per-pixel loss partial ----
        float* outp = out + (size_t)b * DC * HWC + hw;
        float ldist = 0.0f;
        #pragma unroll
        for (int d = 0; d < DC; ++d) {
            float q  = ET[d * ETS + bestk];
            float fx, fy; unpack2(f2[d], fx, fy); (void)fy;
            float dq = __fsub_rn(q, fx);                // fl(q - lat)
            ldist = __fadd_rn(ldist, __fmul_rn(dq, dq));
            outp[d * HWC] = __fadd_rn(fx, dq);          // fl(lat + (q - lat))
        }

        // ---- per-tile deterministic tree reduce -> g_part[tile] ----
        red[tid] = ldist;
        __syncthreads();
        #pragma unroll
        for (int s = TPB / 2; s > 0; s >>= 1) {
            if (tid < s) red[tid] += red[tid + s];
            __syncthreads();
        }
        if (tid == 0) g_part[tile] = red[0];
        __syncthreads();   // red[] reused next tile
    }

    // ---- grid finalize: last CTA reduces the 512 tile partials ----
    __shared__ unsigned s_last;
    __threadfence();
    if (tid == 0) s_last = (atomicAdd(&g_done, 1u) == GRIDP - 1u);
    __syncthreads();

    if (s_last) {
        red[tid] = g_part[tid] + g_part[tid + TPB];
        __syncthreads();
        #pragma unroll
        for (int s = TPB / 2; s > 0; s >>= 1) {
            if (tid < s) red[tid] += red[tid + s];
            __syncthreads();
        }
        if (tid == 0) {
            float m = red[0] / 8388608.0f;                   // exact /2^23
            *loss_out = __fadd_rn(__fmul_rn(m, 0.25f), m);   // fl(0.25m)+m
            g_done = 0;                                      // reset for replay
        }
    }
}

extern "C" void kernel_launch(void* const* d_in, const int* in_sizes, int n_in,
                              void* d_out, int out_size) {
    const float* latents   = (const float*)d_in[0];   // [32,64,64,64] fp32
    const float* embedding = (const float*)d_in[1];   // [512,64] fp32
    float* out  = (float*)d_out;                      // tensor, then loss scalar
    float* loss = out + (out_size - 1);

    cudaFuncSetAttribute(vq_kernel, cudaFuncAttributeMaxDynamicSharedMemorySize, SMEM_BYTES);
    vq_kernel<<<GRIDP, TPB, SMEM_BYTES>>>(latents, embedding, out, loss);
}

// round 5
// speedup vs baseline: 1.7638x; 1.4292x over previous
#include <cuda_runtime.h>
#include <float.h>
#include <stdint.h>

// Fixed problem shape
#define KC      512         // codebook size
#define DC      64          // code dim
#define HWC     4096        // H*W
#define NC      131072      // B*H*W
#define TPB     256
#define PPT     2           // pixels per thread
#define TILE    (TPB*PPT)   // 512 pixels per tile
#define NTILES  (NC/TILE)   // 256 tiles
#define GRIDP   128         // 2 tiles per CTA, perfectly balanced
#define ETS     520         // padded row stride (floats), rows 16B-aligned

// smem floats: ET[64][520] + enorm[512] + red[256]
#define ET_FLOATS   (DC * ETS)
#define SMEM_FLOATS (ET_FLOATS + KC + TPB)
#define SMEM_BYTES  (SMEM_FLOATS * 4)

__device__ float    g_part[NTILES];
__device__ unsigned g_done;         // zero-init; finalizer resets each launch

typedef unsigned long long u64;

__device__ __forceinline__ u64 pack2(float x, float y) {
    u64 r;
    asm("mov.b64 %0, {%1, %2};" : "=l"(r) : "f"(x), "f"(y));
    return r;
}
__device__ __forceinline__ void unpack2(u64 v, float& x, float& y) {
    asm("mov.b64 {%0, %1}, %2;" : "=f"(x), "=f"(y) : "l"(v));
}
__device__ __forceinline__ u64 ffma2(u64 a, u64 b, u64 c) {
    u64 d;
    asm("fma.rn.f32x2 %0, %1, %2, %3;" : "=l"(d) : "l"(a), "l"(b), "l"(c));
    return d;
}

__global__ __launch_bounds__(TPB, 1)
void vq_kernel(const float* __restrict__ latents,
               const float* __restrict__ embedding,
               float* __restrict__ out,
               float* __restrict__ loss_out) {
    extern __shared__ float smem[];
    float* ET    = smem;                 // [64][520], ET[d*ETS + k]
    float* eNorm = smem + ET_FLOATS;     // [512]
    float* red   = eNorm + KC;           // [256]

    const int tid = threadIdx.x;

    // ---- stage transposed codebook once per CTA ----
    {
        const float4* src = reinterpret_cast<const float4*>(embedding);
        #pragma unroll
        for (int i4 = tid; i4 < (KC * DC) / 4; i4 += TPB) {
            float4 v = src[i4];
            int i = i4 * 4;
            int k = i >> 6;
            int d = i & 63;
            ET[(d + 0) * ETS + k] = v.x;
            ET[(d + 1) * ETS + k] = v.y;
            ET[(d + 2) * ETS + k] = v.z;
            ET[(d + 3) * ETS + k] = v.w;
        }
    }
    __syncthreads();

    // ---- enorm_k: sequential d, separate mul/add (XLA reduce emulation) ----
    #pragma unroll
    for (int k = tid; k < KC; k += TPB) {
        float s = 0.0f;
        #pragma unroll
        for (int d = 0; d < DC; ++d) {
            float e = ET[d * ETS + k];
            s = __fadd_rn(s, __fmul_rn(e, e));
        }
        eNorm[k] = s;
    }
    __syncthreads();

    // ---- persistent tile loop: 2 tiles of 512 pixels per CTA ----
    for (int tile = blockIdx.x; tile < NTILES; tile += GRIDP) {
        const int pA = tile * TILE + tid;        // pixel A
        const int pB = pA + TPB;                 // pixel B (same batch block)
        const int bA = pA >> 12, hwA = pA & (HWC - 1);
        const int bB = pB >> 12, hwB = pB & (HWC - 1);
        const float* latA = latents + (size_t)bA * DC * HWC + hwA;
        const float* latB = latents + (size_t)bB * DC * HWC + hwB;

        float fA[DC], fB[DC];
        float fnA = 0.0f, fnB = 0.0f;
        #pragma unroll
        for (int d = 0; d < DC; ++d) {
            fA[d] = latA[d * HWC];
            fB[d] = latB[d * HWC];
            fnA = __fadd_rn(fnA, __fmul_rn(fA[d], fA[d]));
            fnB = __fadd_rn(fnB, __fmul_rn(fB[d], fB[d]));
        }

        float bestA = FLT_MAX, bestB = FLT_MAX;
        int   bkA = 0, bkB = 0;

        // ---- argmin over K, both pixels share every codebook load ----
        #pragma unroll 1
        for (int k0 = 0; k0 < KC; k0 += 16) {
            u64 aA0=0,aA1=0,aA2=0,aA3=0,aA4=0,aA5=0,aA6=0,aA7=0;
            u64 aB0=0,aB1=0,aB2=0,aB3=0,aB4=0,aB5=0,aB6=0,aB7=0;

            #pragma unroll
            for (int d = 0; d < DC; ++d) {
                const ulonglong2* row =
                    reinterpret_cast<const ulonglong2*>(ET + d * ETS + k0);
                ulonglong2 e01 = row[0];
                ulonglong2 e23 = row[1];
                ulonglong2 e45 = row[2];
                ulonglong2 e67 = row[3];
                const u64 mA = pack2(fA[d], fA[d]);
                const u64 mB = pack2(fB[d], fB[d]);
                aA0 = ffma2(mA, e01.x, aA0);  aB0 = ffma2(mB, e01.x, aB0);
                aA1 = ffma2(mA, e01.y, aA1);  aB1 = ffma2(mB, e01.y, aB1);
                aA2 = ffma2(mA, e23.x, aA2);  aB2 = ffma2(mB, e23.x, aB2);
                aA3 = ffma2(mA, e23.y, aA3);  aB3 = ffma2(mB, e23.y, aB3);
                aA4 = ffma2(mA, e45.x, aA4);  aB4 = ffma2(mB, e45.x, aB4);
                aA5 = ffma2(mA, e45.y, aA5);  aB5 = ffma2(mB, e45.y, aB5);
                aA6 = ffma2(mA, e67.x, aA6);  aB6 = ffma2(mB, e67.x, aB6);
                aA7 = ffma2(mA, e67.y, aA7);  aB7 = ffma2(mB, e67.y, aB7);
            }

            float dA[16], dB[16];
            unpack2(aA0,dA[0],dA[1]);   unpack2(aA1,dA[2],dA[3]);
            unpack2(aA2,dA[4],dA[5]);   unpack2(aA3,dA[6],dA[7]);
            unpack2(aA4,dA[8],dA[9]);   unpack2(aA5,dA[10],dA[11]);
            unpack2(aA6,dA[12],dA[13]); unpack2(aA7,dA[14],dA[15]);
            unpack2(aB0,dB[0],dB[1]);   unpack2(aB1,dB[2],dB[3]);
            unpack2(aB2,dB[4],dB[5]);   unpack2(aB3,dB[6],dB[7]);
            unpack2(aB4,dB[8],dB[9]);   unpack2(aB5,dB[10],dB[11]);
            unpack2(aB6,dB[12],dB[13]); unpack2(aB7,dB[14],dB[15]);

            #pragma unroll
            for (int j = 0; j < 16; ++j) {
                int k = k0 + j;
                float en = eNorm[k];
                float sA = __fsub_rn(__fadd_rn(fnA, en), __fmul_rn(2.0f, dA[j]));
                float sB = __fsub_rn(__fadd_rn(fnB, en), __fmul_rn(2.0f, dB[j]));
                bkA = (sA < bestA) ? k : bkA;   bestA = fminf(sA, bestA);
                bkB = (sB < bestB) ? k : bkB;   bestB = fminf(sB, bestB);
            }
        }

        // ---- epilogue: gather codes, STE outputs, per-pixel loss partials ----
        float* outA = out + (size_t)bA * DC * HWC + hwA;
        float* outB = out + (size_t)bB * DC * HWC + hwB;
        float ldist = 0.0f;
        #pragma unroll
        for (int d = 0; d < DC; ++d) {
            float qA = ET[d * ETS + bkA];
            float qB = ET[d * ETS + bkB];
            float dqA = __fsub_rn(qA, fA[d]);
            float dqB = __fsub_rn(qB, fB[d]);
            ldist = __fadd_rn(ldist, __fmul_rn(dqA, dqA));
            ldist = __fadd_rn(ldist, __fmul_rn(dqB, dqB));
            outA[d * HWC] = __fadd_rn(fA[d], dqA);
            outB[d * HWC] = __fadd_rn(fB[d], dqB);
        }

        // ---- per-tile deterministic tree reduce -> g_part[tile] ----
        red[tid] = ldist;
        __syncthreads();
        #pragma unroll
        for (int s = TPB / 2; s > 0; s >>= 1) {
            if (tid < s) red[tid] += red[tid + s];
            __syncthreads();
        }
        if (tid == 0) g_part[tile] = red[0];
        __syncthreads();   // red[] reused next tile
    }

    // ---- grid finalize: last CTA reduces the 256 tile partials ----
    __shared__ unsigned s_last;
    __threadfence();
    if (tid == 0) s_last = (atomicAdd(&g_done, 1u) == GRIDP - 1u);
    __syncthreads();

    if (s_last) {
        red[tid] = g_part[tid];
        __syncthreads();
        #pragma unroll
        for (int s = TPB / 2; s > 0; s >>= 1) {
            if (tid < s) red[tid] += red[tid + s];
            __syncthreads();
        }
        if (tid == 0) {
            float m = red[0] / 8388608.0f;                   // exact /2^23
            *loss_out = __fadd_rn(__fmul_rn(m, 0.25f), m);   // fl(0.25m)+m
            g_done = 0;                                      // reset for replay
        }
    }
}

extern "C" void kernel_launch(void* const* d_in, const int* in_sizes, int n_in,
                              void* d_out, int out_size) {
    const float* latents   = (const float*)d_in[0];   // [32,64,64,64] fp32
    const float* embedding = (const float*)d_in[1];   // [512,64] fp32
    float* out  = (float*)d_out;                      // tensor, then loss scalar
    float* loss = out + (out_size - 1);

    cudaFuncSetAttribute(vq_kernel, cudaFuncAttributeMaxDynamicSharedMemorySize, SMEM_BYTES);
    vq_kernel<<<GRIDP, TPB, SMEM_BYTES>>>(latents, embedding, out, loss);
}